// round 4
// baseline (speedup 1.0000x reference)
#include <cuda_runtime.h>

#define NN 50000
#define DD 128
#define EE 800000
#define BN_EPS 1e-5f

// Scratch (no allocations allowed): two N x D buffers + BN stats
__device__ float g_buf1[NN * DD];   // agg -> h (pre-BN)
__device__ float g_buf2[NN * DD];   // t = relu(h@W1+b1)
__device__ float g_stats[2 * DD];   // [0:128) col sums, [128:256) col sumsq
__device__ float g_scale[DD];
__device__ float g_shift[DD];
__device__ int g_is64;              // 1 if edge_index is int64, 0 if int32

// k_det: probe edge_index dtype. Indices < 50000 < 2^31, so int64 data has
// zero high words at every odd 32-bit position.
__global__ void detect_kernel(const int* __restrict__ ei32) {
    int zeros = 0;
    for (int i = 1; i < 256; i += 2) zeros += (ei32[i] == 0);
    g_is64 = (zeros >= 96) ? 1 : 0;
}

// k0: agg = x (GIN eps=0 -> h = x + sum(msg)), zero stats
__global__ void init_kernel(const float* __restrict__ x) {
    int i = blockIdx.x * blockDim.x + threadIdx.x;
    if (i < NN * DD / 4) {
        ((float4*)g_buf1)[i] = ((const float4*)x)[i];
    }
    if (blockIdx.x == 0 && threadIdx.x < 2 * DD) g_stats[threadIdx.x] = 0.f;
}

// k1: one warp per edge; msg = relu(x[src] + edge_attr); vector-atomic scatter
__global__ void edge_kernel(const float* __restrict__ x,
                            const void* __restrict__ ei,
                            const float* __restrict__ ea) {
    unsigned gt = blockIdx.x * blockDim.x + threadIdx.x;
    unsigned e = gt >> 5;
    int lane = gt & 31;
    if (e >= EE) return;
    long long src, dst;
    if (g_is64) {
        const long long* p = (const long long*)ei;
        src = p[e];
        dst = p[EE + e];
    } else {
        const int* p = (const int*)ei;
        src = p[e];
        dst = p[EE + e];
    }
    if ((unsigned long long)src >= NN || (unsigned long long)dst >= NN) return;
    int c = lane * 4;
    float4 a = *(const float4*)(ea + (size_t)e * DD + c);
    float4 b = *(const float4*)(x + (size_t)src * DD + c);
    float4 v;
    v.x = fmaxf(a.x + b.x, 0.f);
    v.y = fmaxf(a.y + b.y, 0.f);
    v.z = fmaxf(a.z + b.z, 0.f);
    v.w = fmaxf(a.w + b.w, 0.f);
    atomicAdd((float4*)(g_buf1 + (size_t)dst * DD + c), v);
}

// k2/k3: 64x128 output tile per CTA (2 CTAs/SM), 256 threads, 4x8 per thread.
// MODE 0: g_buf2 = relu(g_buf1 @ W + b)
// MODE 1: g_buf1 = resid + g_buf2 @ W + b, and accumulate BN column stats
#define TM 64
template <int MODE>
__global__ void __launch_bounds__(256, 2) gemm_kernel(const float* __restrict__ W,
                                                      const float* __restrict__ bias,
                                                      const float* __restrict__ resid) {
    extern __shared__ float sm[];
    float(*As)[132] = (float(*)[132])sm;           // [64][132] padded
    float* Ws = sm + TM * 132;                     // [128][128]

    const float* A = (MODE == 0) ? g_buf1 : g_buf2;
    float* out = (MODE == 0) ? g_buf2 : g_buf1;

    int tid = threadIdx.x;
    int wrp = tid >> 5, ln = tid & 31;
    int row0 = blockIdx.x * TM;

    // cooperative load: A tile 64 rows (guarded) and full W (128 rows)
#pragma unroll
    for (int rr = 0; rr < 8; rr++) {
        int r = wrp * 8 + rr;          // 0..63
        int gr = row0 + r;
        float4 av = make_float4(0.f, 0.f, 0.f, 0.f);
        if (gr < NN) av = *(const float4*)(A + (size_t)gr * DD + ln * 4);
        *(float4*)&As[r][ln * 4] = av;
    }
#pragma unroll
    for (int rr = 0; rr < 16; rr++) {
        int r = wrp * 16 + rr;         // 0..127
        *(float4*)&Ws[r * DD + ln * 4] = *(const float4*)(W + (size_t)r * DD + ln * 4);
    }
    __syncthreads();

    int ty = tid >> 4, tx = tid & 15;
    int m0 = ty * 4, n0 = tx * 8;
    float acc[4][8];
#pragma unroll
    for (int i = 0; i < 4; i++)
#pragma unroll
        for (int j = 0; j < 8; j++) acc[i][j] = 0.f;

#pragma unroll 4
    for (int k = 0; k < 128; k++) {
        float a[4];
#pragma unroll
        for (int i = 0; i < 4; i++) a[i] = As[m0 + i][k];
        float4 w0 = *(float4*)&Ws[k * DD + n0];
        float4 w1 = *(float4*)&Ws[k * DD + n0 + 4];
        float w[8] = {w0.x, w0.y, w0.z, w0.w, w1.x, w1.y, w1.z, w1.w};
#pragma unroll
        for (int i = 0; i < 4; i++)
#pragma unroll
            for (int j = 0; j < 8; j++) acc[i][j] += a[i] * w[j];
    }

    float bl[8];
#pragma unroll
    for (int j = 0; j < 8; j++) bl[j] = bias[n0 + j];

    if (MODE == 0) {
#pragma unroll
        for (int i = 0; i < 4; i++) {
            int gr = row0 + m0 + i;
            if (gr < NN) {
                float4 o0, o1;
                o0.x = fmaxf(acc[i][0] + bl[0], 0.f);
                o0.y = fmaxf(acc[i][1] + bl[1], 0.f);
                o0.z = fmaxf(acc[i][2] + bl[2], 0.f);
                o0.w = fmaxf(acc[i][3] + bl[3], 0.f);
                o1.x = fmaxf(acc[i][4] + bl[4], 0.f);
                o1.y = fmaxf(acc[i][5] + bl[5], 0.f);
                o1.z = fmaxf(acc[i][6] + bl[6], 0.f);
                o1.w = fmaxf(acc[i][7] + bl[7], 0.f);
                *(float4*)(out + (size_t)gr * DD + n0) = o0;
                *(float4*)(out + (size_t)gr * DD + n0 + 4) = o1;
            }
        }
    } else {
        float csum[8], csq[8];
#pragma unroll
        for (int j = 0; j < 8; j++) { csum[j] = 0.f; csq[j] = 0.f; }
#pragma unroll
        for (int i = 0; i < 4; i++) {
            int gr = row0 + m0 + i;
            if (gr < NN) {
                float4 r0 = *(const float4*)(resid + (size_t)gr * DD + n0);
                float4 r1 = *(const float4*)(resid + (size_t)gr * DD + n0 + 4);
                float h[8];
                h[0] = acc[i][0] + bl[0] + r0.x;
                h[1] = acc[i][1] + bl[1] + r0.y;
                h[2] = acc[i][2] + bl[2] + r0.z;
                h[3] = acc[i][3] + bl[3] + r0.w;
                h[4] = acc[i][4] + bl[4] + r1.x;
                h[5] = acc[i][5] + bl[5] + r1.y;
                h[6] = acc[i][6] + bl[6] + r1.z;
                h[7] = acc[i][7] + bl[7] + r1.w;
                *(float4*)(out + (size_t)gr * DD + n0) = make_float4(h[0], h[1], h[2], h[3]);
                *(float4*)(out + (size_t)gr * DD + n0 + 4) = make_float4(h[4], h[5], h[6], h[7]);
#pragma unroll
                for (int j = 0; j < 8; j++) {
                    csum[j] += h[j];
                    csq[j] += h[j] * h[j];
                }
            }
        }
        __syncthreads();  // done reading As/Ws; reuse smem for stats
        float* s = sm;    // [256]
        if (tid < 256) s[tid] = 0.f;
        __syncthreads();
#pragma unroll
        for (int j = 0; j < 8; j++) {
            atomicAdd(&s[n0 + j], csum[j]);
            atomicAdd(&s[DD + n0 + j], csq[j]);
        }
        __syncthreads();
        if (tid < 256) atomicAdd(&g_stats[tid], s[tid]);
    }
}

// k4: per-column BN scale/shift
__global__ void finalize_kernel(const float* __restrict__ gamma,
                                const float* __restrict__ beta) {
    int c = threadIdx.x;
    float mean = g_stats[c] * (1.0f / NN);
    float var = g_stats[DD + c] * (1.0f / NN) - mean * mean;
    float sc = rsqrtf(var + BN_EPS) * gamma[c];
    g_scale[c] = sc;
    g_shift[c] = beta[c] - mean * sc;
}

// k5: out = h * scale + shift
__global__ void norm_kernel(float* __restrict__ out) {
    int i = blockIdx.x * blockDim.x + threadIdx.x;
    if (i >= NN * DD / 4) return;
    float4 v = ((const float4*)g_buf1)[i];
    float4 sc = ((const float4*)g_scale)[i & 31];
    float4 sh = ((const float4*)g_shift)[i & 31];
    v.x = v.x * sc.x + sh.x;
    v.y = v.y * sc.y + sh.y;
    v.z = v.z * sc.z + sh.z;
    v.w = v.w * sc.w + sh.w;
    ((float4*)out)[i] = v;
}

extern "C" void kernel_launch(void* const* d_in, const int* in_sizes, int n_in,
                              void* d_out, int out_size) {
    const float* x = (const float*)d_in[0];
    const void* ei = d_in[1];
    const float* ea = (const float*)d_in[2];
    const float* W1 = (const float*)d_in[3];
    const float* b1 = (const float*)d_in[4];
    const float* W2 = (const float*)d_in[5];
    const float* b2 = (const float*)d_in[6];
    const float* gamma = (const float*)d_in[7];
    const float* beta = (const float*)d_in[8];
    float* out = (float*)d_out;

    const int smem = (TM * 132 + 128 * 128) * 4;  // 99328 B -> 2 CTAs/SM
    cudaFuncSetAttribute(gemm_kernel<0>, cudaFuncAttributeMaxDynamicSharedMemorySize, smem);
    cudaFuncSetAttribute(gemm_kernel<1>, cudaFuncAttributeMaxDynamicSharedMemorySize, smem);

    detect_kernel<<<1, 1>>>((const int*)ei);
    init_kernel<<<(NN * DD / 4 + 255) / 256, 256>>>(x);
    edge_kernel<<<(EE * 32) / 256, 256>>>(x, ei, ea);
    gemm_kernel<0><<<(NN + TM - 1) / TM, 256, smem>>>(W1, b1, nullptr);
    gemm_kernel<1><<<(NN + TM - 1) / TM, 256, smem>>>(W2, b2, x);
    finalize_kernel<<<1, DD>>>(gamma, beta);
    norm_kernel<<<(NN * DD / 4 + 255) / 256, 256>>>(out);
}

// round 6
// speedup vs baseline: 1.1100x; 1.1100x over previous
#include <cuda_runtime.h>
#include <cuda_bf16.h>
#include <cstdint>

#define NN 50000
#define DD 128
#define EE 800000
#define BN_EPS 1e-5f

// ---------------- scratch (no allocs allowed) ----------------
__device__ float g_buf1[NN * DD];          // agg -> h (pre-BN)
__device__ float g_buf2[NN * DD];          // t = relu(h@W1+b1)
__device__ float g_stats[2 * DD];          // col sums / sumsq
__device__ float g_scale[DD];
__device__ float g_shift[DD];
__device__ int g_is64;
__device__ __nv_bfloat16 g_w1hi[DD * DD];  // W^T hi/lo splits, [n][k] bf16
__device__ __nv_bfloat16 g_w1lo[DD * DD];
__device__ __nv_bfloat16 g_w2hi[DD * DD];
__device__ __nv_bfloat16 g_w2lo[DD * DD];

// ---------------- helpers ----------------
__device__ __forceinline__ uint32_t smem_u32(const void* p) {
    uint32_t a;
    asm("{ .reg .u64 t; cvta.to.shared.u64 t, %1; cvt.u32.u64 %0, t; }" : "=r"(a) : "l"(p));
    return a;
}
#define LDSM4(r, addr)                                                        \
    asm volatile("ldmatrix.sync.aligned.m8n8.x4.shared.b16 {%0,%1,%2,%3}, [%4];" \
                 : "=r"((r)[0]), "=r"((r)[1]), "=r"((r)[2]), "=r"((r)[3])     \
                 : "r"(addr))
#define MMA(ac, a, b0, b1)                                                    \
    asm volatile(                                                             \
        "mma.sync.aligned.m16n8k16.row.col.f32.bf16.bf16.f32 "                \
        "{%0,%1,%2,%3}, {%4,%5,%6,%7}, {%8,%9}, {%0,%1,%2,%3};"               \
        : "+f"((ac)[0]), "+f"((ac)[1]), "+f"((ac)[2]), "+f"((ac)[3])          \
        : "r"((a)[0]), "r"((a)[1]), "r"((a)[2]), "r"((a)[3]), "r"(b0), "r"(b1))

// ---------------- k_det: edge_index dtype probe ----------------
__global__ void detect_kernel(const int* __restrict__ ei32) {
    int zeros = 0;
    for (int i = 1; i < 256; i += 2) zeros += (ei32[i] == 0);
    g_is64 = (zeros >= 96) ? 1 : 0;
}

// ---------------- prep: W -> transposed bf16 hi/lo splits [n][k] ----------------
__global__ void prep_w(const float* __restrict__ W1, const float* __restrict__ W2) {
    const float* W = blockIdx.y ? W2 : W1;
    __nv_bfloat16* hi = blockIdx.y ? g_w2hi : g_w1hi;
    __nv_bfloat16* lo = blockIdx.y ? g_w2lo : g_w1lo;
    int k = blockIdx.x, n = threadIdx.x;
    float v = W[k * DD + n];
    __nv_bfloat16 h = __float2bfloat16(v);
    hi[n * DD + k] = h;
    lo[n * DD + k] = __float2bfloat16(v - __bfloat162float(h));
}

// ---------------- k0: agg = x, zero stats ----------------
__global__ void init_kernel(const float* __restrict__ x) {
    int i = blockIdx.x * blockDim.x + threadIdx.x;
    if (i < NN * DD / 4) ((float4*)g_buf1)[i] = ((const float4*)x)[i];
    if (blockIdx.x == 0 && threadIdx.x < 2 * DD) g_stats[threadIdx.x] = 0.f;
}

// ---------------- k1: edge scatter ----------------
__global__ void edge_kernel(const float* __restrict__ x,
                            const void* __restrict__ ei,
                            const float* __restrict__ ea) {
    unsigned gt = blockIdx.x * blockDim.x + threadIdx.x;
    unsigned e = gt >> 5;
    int lane = gt & 31;
    if (e >= EE) return;
    long long src, dst;
    if (g_is64) {
        const long long* p = (const long long*)ei;
        src = p[e];
        dst = p[EE + e];
    } else {
        const int* p = (const int*)ei;
        src = p[e];
        dst = p[EE + e];
    }
    if ((unsigned long long)src >= NN || (unsigned long long)dst >= NN) return;
    int c = lane * 4;
    float4 a = __ldcs((const float4*)(ea + (size_t)e * DD + c));  // streamed once
    float4 b = __ldg((const float4*)(x + (size_t)src * DD + c));
    float4 v;
    v.x = fmaxf(a.x + b.x, 0.f);
    v.y = fmaxf(a.y + b.y, 0.f);
    v.z = fmaxf(a.z + b.z, 0.f);
    v.w = fmaxf(a.w + b.w, 0.f);
    atomicAdd((float4*)(g_buf1 + (size_t)dst * DD + c), v);
}

// ---------------- HMMA GEMM: 64x128 out tile per CTA, 2 CTAs/SM ----------------
#define AST 136
#define OF_AHI 1024u
#define OF_ALO (1024u + 17408u)
#define OF_BHI (1024u + 2u * 17408u)
#define OF_BLO (1024u + 2u * 17408u + 34816u)
#define MM_SMEM (1024 + 2 * 17408 + 2 * 34816)

template <int MODE>
__global__ void __launch_bounds__(256, 2) mm_kernel(const float* __restrict__ bias,
                                                    const float* __restrict__ resid) {
    extern __shared__ char smem[];
    const uint32_t sb = smem_u32(smem);
    float* sbias = (float*)smem;
    const int tid = threadIdx.x, wid = tid >> 5, ln = tid & 31;
    const int row0 = blockIdx.x * 64;

    const float* A = MODE ? g_buf2 : g_buf1;
    float* out = MODE ? g_buf1 : g_buf2;
    const __nv_bfloat16* Bhi = MODE ? g_w2hi : g_w1hi;
    const __nv_bfloat16* Blo = MODE ? g_w2lo : g_w1lo;

    if (tid < 128) sbias[tid] = bias[tid];

    // A: 64 rows fp32 -> bf16 hi/lo, padded row-major [m][AST]
    {
        __nv_bfloat16* sAh = (__nv_bfloat16*)(smem + OF_AHI);
        __nv_bfloat16* sAl = (__nv_bfloat16*)(smem + OF_ALO);
#pragma unroll
        for (int rr = 0; rr < 8; rr++) {
            int r = wid * 8 + rr;
            int gr = row0 + r;
            float4 v = make_float4(0.f, 0.f, 0.f, 0.f);
            if (gr < NN) v = *(const float4*)(A + (size_t)gr * DD + ln * 4);
            __nv_bfloat16 hx = __float2bfloat16(v.x), hy = __float2bfloat16(v.y);
            __nv_bfloat16 hz = __float2bfloat16(v.z), hw = __float2bfloat16(v.w);
            __nv_bfloat162 hi0 = __halves2bfloat162(hx, hy);
            __nv_bfloat162 hi1 = __halves2bfloat162(hz, hw);
            __nv_bfloat162 lo0 = __halves2bfloat162(
                __float2bfloat16(v.x - __bfloat162float(hx)),
                __float2bfloat16(v.y - __bfloat162float(hy)));
            __nv_bfloat162 lo1 = __halves2bfloat162(
                __float2bfloat16(v.z - __bfloat162float(hz)),
                __float2bfloat16(v.w - __bfloat162float(hw)));
            int o = r * AST + ln * 4;
            *(__nv_bfloat162*)(sAh + o) = hi0;
            *(__nv_bfloat162*)(sAh + o + 2) = hi1;
            *(__nv_bfloat162*)(sAl + o) = lo0;
            *(__nv_bfloat162*)(sAl + o + 2) = lo1;
        }
    }
    // B: bf16 [n][k] -> padded [n][AST]
    {
        __nv_bfloat16* sBh = (__nv_bfloat16*)(smem + OF_BHI);
        __nv_bfloat16* sBl = (__nv_bfloat16*)(smem + OF_BLO);
#pragma unroll
        for (int rr = 0; rr < 16; rr++) {
            int n = wid * 16 + rr;
            uint2 vh = *(const uint2*)(Bhi + (size_t)n * DD + ln * 4);
            uint2 vl = *(const uint2*)(Blo + (size_t)n * DD + ln * 4);
            int o = n * AST + ln * 4;
            *(uint32_t*)((char*)sBh + (size_t)o * 2) = vh.x;
            *(uint32_t*)((char*)sBh + (size_t)o * 2 + 4) = vh.y;
            *(uint32_t*)((char*)sBl + (size_t)o * 2) = vl.x;
            *(uint32_t*)((char*)sBl + (size_t)o * 2 + 4) = vl.y;
        }
    }
    __syncthreads();

    const int m0 = (wid & 3) * 16;
    const int cb = (wid >> 2) * 64;
    const uint32_t a_off =
        (uint32_t)((m0 + ((ln >> 3) & 1) * 8 + (ln & 7)) * AST + ((ln >> 4) & 1) * 8) * 2u;
    const uint32_t b_off =
        (uint32_t)((cb + ((ln >> 4) & 1) * 8 + (ln & 7)) * AST + ((ln >> 3) & 1) * 8) * 2u;
    const uint32_t aAh = sb + OF_AHI + a_off, aAl = sb + OF_ALO + a_off;
    const uint32_t aBh = sb + OF_BHI + b_off, aBl = sb + OF_BLO + b_off;

    float acc[8][4];
#pragma unroll
    for (int f = 0; f < 8; f++)
#pragma unroll
        for (int j = 0; j < 4; j++) acc[f][j] = 0.f;

#pragma unroll
    for (int ks = 0; ks < 8; ks++) {
        const uint32_t kb = ks * 32u;
        uint32_t ah[4], al[4];
        LDSM4(ah, aAh + kb);
        LDSM4(al, aAl + kb);
#pragma unroll
        for (int nb = 0; nb < 4; nb++) {
            uint32_t bh[4], bl[4];
            const uint32_t bo = (uint32_t)(nb * 16 * AST) * 2u + kb;
            LDSM4(bh, aBh + bo);
            LDSM4(bl, aBl + bo);
            MMA(acc[2 * nb], ah, bh[0], bh[1]);
            MMA(acc[2 * nb + 1], ah, bh[2], bh[3]);
            MMA(acc[2 * nb], ah, bl[0], bl[1]);
            MMA(acc[2 * nb + 1], ah, bl[2], bl[3]);
            MMA(acc[2 * nb], al, bh[0], bh[1]);
            MMA(acc[2 * nb + 1], al, bh[2], bh[3]);
        }
    }

    const int gr0 = row0 + m0 + (ln >> 2);
    const int gr1 = gr0 + 8;
#pragma unroll
    for (int f = 0; f < 8; f++) {
        const int c = cb + f * 8 + (ln & 3) * 2;
        float2 v0 = make_float2(acc[f][0] + sbias[c], acc[f][1] + sbias[c + 1]);
        float2 v1 = make_float2(acc[f][2] + sbias[c], acc[f][3] + sbias[c + 1]);
        if (MODE == 0) {
            v0.x = fmaxf(v0.x, 0.f); v0.y = fmaxf(v0.y, 0.f);
            v1.x = fmaxf(v1.x, 0.f); v1.y = fmaxf(v1.y, 0.f);
            if (gr0 < NN) *(float2*)(out + (size_t)gr0 * DD + c) = v0;
            if (gr1 < NN) *(float2*)(out + (size_t)gr1 * DD + c) = v1;
        } else {
            if (gr0 < NN) {
                float2 r = *(const float2*)(resid + (size_t)gr0 * DD + c);
                v0.x += r.x; v0.y += r.y;
                *(float2*)(out + (size_t)gr0 * DD + c) = v0;
            }
            if (gr1 < NN) {
                float2 r = *(const float2*)(resid + (size_t)gr1 * DD + c);
                v1.x += r.x; v1.y += r.y;
                *(float2*)(out + (size_t)gr1 * DD + c) = v1;
            }
        }
    }
}

// ---------------- BN stats over g_buf1 ----------------
__global__ void stats_kernel() {
    __shared__ float s[2 * DD];
    int tid = threadIdx.x;
    if (tid < 2 * DD) s[tid] = 0.f;
    __syncthreads();
    float cs[4] = {0.f, 0.f, 0.f, 0.f}, cq[4] = {0.f, 0.f, 0.f, 0.f};
    int stride = gridDim.x * blockDim.x;
    for (int i = blockIdx.x * blockDim.x + tid; i < NN * DD / 4; i += stride) {
        float4 v = ((const float4*)g_buf1)[i];
        cs[0] += v.x; cq[0] += v.x * v.x;
        cs[1] += v.y; cq[1] += v.y * v.y;
        cs[2] += v.z; cq[2] += v.z * v.z;
        cs[3] += v.w; cq[3] += v.w * v.w;
    }
    int c4 = (tid & 31) * 4;
#pragma unroll
    for (int j = 0; j < 4; j++) {
        atomicAdd(&s[c4 + j], cs[j]);
        atomicAdd(&s[DD + c4 + j], cq[j]);
    }
    __syncthreads();
    if (tid < 2 * DD) atomicAdd(&g_stats[tid], s[tid]);
}

// ---------------- finalize + normalize ----------------
__global__ void finalize_kernel(const float* __restrict__ gamma,
                                const float* __restrict__ beta) {
    int c = threadIdx.x;
    float mean = g_stats[c] * (1.0f / NN);
    float var = g_stats[DD + c] * (1.0f / NN) - mean * mean;
    float sc = rsqrtf(var + BN_EPS) * gamma[c];
    g_scale[c] = sc;
    g_shift[c] = beta[c] - mean * sc;
}

__global__ void norm_kernel(float* __restrict__ out) {
    int i = blockIdx.x * blockDim.x + threadIdx.x;
    if (i >= NN * DD / 4) return;
    float4 v = ((const float4*)g_buf1)[i];
    float4 sc = ((const float4*)g_scale)[i & 31];
    float4 sh = ((const float4*)g_shift)[i & 31];
    v.x = v.x * sc.x + sh.x;
    v.y = v.y * sc.y + sh.y;
    v.z = v.z * sc.z + sh.z;
    v.w = v.w * sc.w + sh.w;
    ((float4*)out)[i] = v;
}

extern "C" void kernel_launch(void* const* d_in, const int* in_sizes, int n_in,
                              void* d_out, int out_size) {
    const float* x = (const float*)d_in[0];
    const void* ei = d_in[1];
    const float* ea = (const float*)d_in[2];
    const float* W1 = (const float*)d_in[3];
    const float* b1 = (const float*)d_in[4];
    const float* W2 = (const float*)d_in[5];
    const float* b2 = (const float*)d_in[6];
    const float* gamma = (const float*)d_in[7];
    const float* beta = (const float*)d_in[8];
    float* out = (float*)d_out;

    cudaFuncSetAttribute(mm_kernel<0>, cudaFuncAttributeMaxDynamicSharedMemorySize, MM_SMEM);
    cudaFuncSetAttribute(mm_kernel<1>, cudaFuncAttributeMaxDynamicSharedMemorySize, MM_SMEM);

    detect_kernel<<<1, 1>>>((const int*)ei);
    prep_w<<<dim3(DD, 2), DD>>>(W1, W2);
    init_kernel<<<(NN * DD / 4 + 255) / 256, 256>>>(x);
    edge_kernel<<<(EE * 32) / 256, 256>>>(x, ei, ea);
    mm_kernel<0><<<(NN + 63) / 64, 256, MM_SMEM>>>(b1, x);
    mm_kernel<1><<<(NN + 63) / 64, 256, MM_SMEM>>>(b2, x);
    stats_kernel<<<592, 256>>>();
    finalize_kernel<<<1, DD>>>(gamma, beta);
    norm_kernel<<<(NN * DD / 4 + 255) / 256, 256>>>(out);
}

// round 7
// speedup vs baseline: 1.3702x; 1.2345x over previous
#include <cuda_runtime.h>
#include <cuda_bf16.h>
#include <cstdint>

#define NN 50000
#define DD 128
#define EE 800000
#define BN_EPS 1e-5f

// ---------------- scratch (no allocs allowed) ----------------
__device__ float g_buf1[NN * DD];          // agg -> h (pre-BN)
__device__ float g_buf2[NN * DD];          // t = relu(h@W1+b1)
__device__ float g_stats[2 * DD];
__device__ float g_scale[DD];
__device__ float g_shift[DD];
__device__ int g_is64;
__device__ __nv_bfloat16 g_w1hi[DD * DD];  // W^T hi/lo splits, [n][k] bf16
__device__ __nv_bfloat16 g_w1lo[DD * DD];
__device__ __nv_bfloat16 g_w2hi[DD * DD];
__device__ __nv_bfloat16 g_w2lo[DD * DD];
// CSR scratch
__device__ int g_src[EE];
__device__ int g_dst[EE];
__device__ int g_cnt[NN];
__device__ int g_off[NN];
__device__ int g_cursor[NN];
__device__ int g_eid[EE];

// ---------------- helpers ----------------
__device__ __forceinline__ uint32_t smem_u32(const void* p) {
    uint32_t a;
    asm("{ .reg .u64 t; cvta.to.shared.u64 t, %1; cvt.u32.u64 %0, t; }" : "=r"(a) : "l"(p));
    return a;
}
#define LDSM4(r, addr)                                                        \
    asm volatile("ldmatrix.sync.aligned.m8n8.x4.shared.b16 {%0,%1,%2,%3}, [%4];" \
                 : "=r"((r)[0]), "=r"((r)[1]), "=r"((r)[2]), "=r"((r)[3])     \
                 : "r"(addr))
#define MMA(ac, a, b0, b1)                                                    \
    asm volatile(                                                             \
        "mma.sync.aligned.m16n8k16.row.col.f32.bf16.bf16.f32 "                \
        "{%0,%1,%2,%3}, {%4,%5,%6,%7}, {%8,%9}, {%0,%1,%2,%3};"               \
        : "+f"((ac)[0]), "+f"((ac)[1]), "+f"((ac)[2]), "+f"((ac)[3])          \
        : "r"((a)[0]), "r"((a)[1]), "r"((a)[2]), "r"((a)[3]), "r"(b0), "r"(b1))

// ---------------- k_det: edge_index dtype probe ----------------
__global__ void detect_kernel(const int* __restrict__ ei32) {
    int zeros = 0;
    for (int i = 1; i < 256; i += 2) zeros += (ei32[i] == 0);
    g_is64 = (zeros >= 96) ? 1 : 0;
}

// ---------------- zero counters + stats (runs every replay) ----------------
__global__ void zero_kernel() {
    int i = blockIdx.x * blockDim.x + threadIdx.x;
    if (i < NN) g_cnt[i] = 0;
    if (i < 2 * DD) g_stats[i] = 0.f;
}

// ---------------- prep: W -> transposed bf16 hi/lo splits [n][k] ----------------
__global__ void prep_w(const float* __restrict__ W1, const float* __restrict__ W2) {
    const float* W = blockIdx.y ? W2 : W1;
    __nv_bfloat16* hi = blockIdx.y ? g_w2hi : g_w1hi;
    __nv_bfloat16* lo = blockIdx.y ? g_w2lo : g_w1lo;
    int k = blockIdx.x, n = threadIdx.x;
    float v = W[k * DD + n];
    __nv_bfloat16 h = __float2bfloat16(v);
    hi[n * DD + k] = h;
    lo[n * DD + k] = __float2bfloat16(v - __bfloat162float(h));
}

// ---------------- convert: edge_index -> int32 + dst histogram ----------------
__global__ void convert_kernel(const void* __restrict__ ei) {
    int e = blockIdx.x * blockDim.x + threadIdx.x;
    if (e >= EE) return;
    long long s, d;
    if (g_is64) {
        const long long* p = (const long long*)ei;
        s = p[e];
        d = p[EE + e];
    } else {
        const int* p = (const int*)ei;
        s = p[e];
        d = p[EE + e];
    }
    int si = (int)s, di = (int)d;
    if ((unsigned)si >= NN) si = 0;
    if ((unsigned)di >= NN) di = 0;
    g_src[e] = si;
    g_dst[e] = di;
    atomicAdd(&g_cnt[di], 1);
}

// ---------------- scan: exclusive prefix over g_cnt (1 CTA, 1024 thr) ----------------
__global__ void scan_kernel() {
    __shared__ int warp_sums[32];
    __shared__ int s_carry;
    int tid = threadIdx.x;
    if (tid == 0) s_carry = 0;
    __syncthreads();
    for (int base = 0; base < NN; base += 1024) {
        int i = base + tid;
        int v = (i < NN) ? g_cnt[i] : 0;
        int incl = v;
#pragma unroll
        for (int d = 1; d < 32; d <<= 1) {
            int t = __shfl_up_sync(0xFFFFFFFFu, incl, d);
            if ((tid & 31) >= d) incl += t;
        }
        if ((tid & 31) == 31) warp_sums[tid >> 5] = incl;
        __syncthreads();
        if (tid < 32) {
            int w = warp_sums[tid];
            int ws = w;
#pragma unroll
            for (int d = 1; d < 32; d <<= 1) {
                int t = __shfl_up_sync(0xFFFFFFFFu, ws, d);
                if (tid >= d) ws += t;
            }
            warp_sums[tid] = ws - w;  // exclusive warp offset
        }
        __syncthreads();
        int excl = incl - v + warp_sums[tid >> 5] + s_carry;
        if (i < NN) {
            g_off[i] = excl;
            g_cursor[i] = excl;
        }
        __syncthreads();
        if (tid == 1023) s_carry = excl + v;
        __syncthreads();
    }
}

// ---------------- scatter: bucket edge ids by dst ----------------
__global__ void scatter_kernel() {
    int e = blockIdx.x * blockDim.x + threadIdx.x;
    if (e >= EE) return;
    int d = g_dst[e];
    int pos = atomicAdd(&g_cursor[d], 1);
    g_eid[pos] = e;
}

// ---------------- aggregate: warp per node, no float atomics ----------------
__global__ void agg_kernel(const float* __restrict__ x,
                           const float* __restrict__ ea) {
    int w = (blockIdx.x * blockDim.x + threadIdx.x) >> 5;
    int ln = threadIdx.x & 31;
    if (w >= NN) return;
    int beg = g_off[w];
    int cnt = g_cnt[w];
    int c = ln * 4;
    float4 acc = __ldg((const float4*)(x + (size_t)w * DD + c));  // h = x + agg
    for (int i = 0; i < cnt; i++) {
        int e = __ldg(&g_eid[beg + i]);
        int s = __ldg(&g_src[e]);
        float4 a = __ldcs((const float4*)(ea + (size_t)e * DD + c));
        float4 b = __ldg((const float4*)(x + (size_t)s * DD + c));
        acc.x += fmaxf(a.x + b.x, 0.f);
        acc.y += fmaxf(a.y + b.y, 0.f);
        acc.z += fmaxf(a.z + b.z, 0.f);
        acc.w += fmaxf(a.w + b.w, 0.f);
    }
    *(float4*)(g_buf1 + (size_t)w * DD + c) = acc;
}

// ---------------- HMMA GEMM: 64x128 out tile per CTA, 2 CTAs/SM ----------------
#define AST 136
#define OF_AHI 1024u
#define OF_ALO (1024u + 17408u)
#define OF_BHI (1024u + 2u * 17408u)
#define OF_BLO (1024u + 2u * 17408u + 34816u)
#define MM_SMEM (1024 + 2 * 17408 + 2 * 34816)

template <int MODE>
__global__ void __launch_bounds__(256, 2) mm_kernel(const float* __restrict__ bias,
                                                    const float* __restrict__ resid) {
    extern __shared__ char smem[];
    const uint32_t sb = smem_u32(smem);
    float* sbias = (float*)smem;
    const int tid = threadIdx.x, wid = tid >> 5, ln = tid & 31;
    const int row0 = blockIdx.x * 64;

    const float* A = MODE ? g_buf2 : g_buf1;
    float* out = MODE ? g_buf1 : g_buf2;
    const __nv_bfloat16* Bhi = MODE ? g_w2hi : g_w1hi;
    const __nv_bfloat16* Blo = MODE ? g_w2lo : g_w1lo;

    if (tid < 128) sbias[tid] = bias[tid];

    {
        __nv_bfloat16* sAh = (__nv_bfloat16*)(smem + OF_AHI);
        __nv_bfloat16* sAl = (__nv_bfloat16*)(smem + OF_ALO);
#pragma unroll
        for (int rr = 0; rr < 8; rr++) {
            int r = wid * 8 + rr;
            int gr = row0 + r;
            float4 v = make_float4(0.f, 0.f, 0.f, 0.f);
            if (gr < NN) v = *(const float4*)(A + (size_t)gr * DD + ln * 4);
            __nv_bfloat16 hx = __float2bfloat16(v.x), hy = __float2bfloat16(v.y);
            __nv_bfloat16 hz = __float2bfloat16(v.z), hw = __float2bfloat16(v.w);
            __nv_bfloat162 hi0 = __halves2bfloat162(hx, hy);
            __nv_bfloat162 hi1 = __halves2bfloat162(hz, hw);
            __nv_bfloat162 lo0 = __halves2bfloat162(
                __float2bfloat16(v.x - __bfloat162float(hx)),
                __float2bfloat16(v.y - __bfloat162float(hy)));
            __nv_bfloat162 lo1 = __halves2bfloat162(
                __float2bfloat16(v.z - __bfloat162float(hz)),
                __float2bfloat16(v.w - __bfloat162float(hw)));
            int o = r * AST + ln * 4;
            *(__nv_bfloat162*)(sAh + o) = hi0;
            *(__nv_bfloat162*)(sAh + o + 2) = hi1;
            *(__nv_bfloat162*)(sAl + o) = lo0;
            *(__nv_bfloat162*)(sAl + o + 2) = lo1;
        }
    }
    {
        __nv_bfloat16* sBh = (__nv_bfloat16*)(smem + OF_BHI);
        __nv_bfloat16* sBl = (__nv_bfloat16*)(smem + OF_BLO);
#pragma unroll
        for (int rr = 0; rr < 16; rr++) {
            int n = wid * 16 + rr;
            uint2 vh = *(const uint2*)(Bhi + (size_t)n * DD + ln * 4);
            uint2 vl = *(const uint2*)(Blo + (size_t)n * DD + ln * 4);
            int o = n * AST + ln * 4;
            *(uint32_t*)((char*)sBh + (size_t)o * 2) = vh.x;
            *(uint32_t*)((char*)sBh + (size_t)o * 2 + 4) = vh.y;
            *(uint32_t*)((char*)sBl + (size_t)o * 2) = vl.x;
            *(uint32_t*)((char*)sBl + (size_t)o * 2 + 4) = vl.y;
        }
    }
    __syncthreads();

    const int m0 = (wid & 3) * 16;
    const int cb = (wid >> 2) * 64;
    const uint32_t a_off =
        (uint32_t)((m0 + ((ln >> 3) & 1) * 8 + (ln & 7)) * AST + ((ln >> 4) & 1) * 8) * 2u;
    const uint32_t b_off =
        (uint32_t)((cb + ((ln >> 4) & 1) * 8 + (ln & 7)) * AST + ((ln >> 3) & 1) * 8) * 2u;
    const uint32_t aAh = sb + OF_AHI + a_off, aAl = sb + OF_ALO + a_off;
    const uint32_t aBh = sb + OF_BHI + b_off, aBl = sb + OF_BLO + b_off;

    float acc[8][4];
#pragma unroll
    for (int f = 0; f < 8; f++)
#pragma unroll
        for (int j = 0; j < 4; j++) acc[f][j] = 0.f;

#pragma unroll
    for (int ks = 0; ks < 8; ks++) {
        const uint32_t kb = ks * 32u;
        uint32_t ah[4], al[4];
        LDSM4(ah, aAh + kb);
        LDSM4(al, aAl + kb);
#pragma unroll
        for (int nb = 0; nb < 4; nb++) {
            uint32_t bh[4], bl[4];
            const uint32_t bo = (uint32_t)(nb * 16 * AST) * 2u + kb;
            LDSM4(bh, aBh + bo);
            LDSM4(bl, aBl + bo);
            MMA(acc[2 * nb], ah, bh[0], bh[1]);
            MMA(acc[2 * nb + 1], ah, bh[2], bh[3]);
            MMA(acc[2 * nb], ah, bl[0], bl[1]);
            MMA(acc[2 * nb + 1], ah, bl[2], bl[3]);
            MMA(acc[2 * nb], al, bh[0], bh[1]);
            MMA(acc[2 * nb + 1], al, bh[2], bh[3]);
        }
    }

    const int gr0 = row0 + m0 + (ln >> 2);
    const int gr1 = gr0 + 8;
#pragma unroll
    for (int f = 0; f < 8; f++) {
        const int c = cb + f * 8 + (ln & 3) * 2;
        float2 v0 = make_float2(acc[f][0] + sbias[c], acc[f][1] + sbias[c + 1]);
        float2 v1 = make_float2(acc[f][2] + sbias[c], acc[f][3] + sbias[c + 1]);
        if (MODE == 0) {
            v0.x = fmaxf(v0.x, 0.f); v0.y = fmaxf(v0.y, 0.f);
            v1.x = fmaxf(v1.x, 0.f); v1.y = fmaxf(v1.y, 0.f);
            if (gr0 < NN) *(float2*)(out + (size_t)gr0 * DD + c) = v0;
            if (gr1 < NN) *(float2*)(out + (size_t)gr1 * DD + c) = v1;
        } else {
            if (gr0 < NN) {
                float2 r = *(const float2*)(resid + (size_t)gr0 * DD + c);
                v0.x += r.x; v0.y += r.y;
                *(float2*)(out + (size_t)gr0 * DD + c) = v0;
            }
            if (gr1 < NN) {
                float2 r = *(const float2*)(resid + (size_t)gr1 * DD + c);
                v1.x += r.x; v1.y += r.y;
                *(float2*)(out + (size_t)gr1 * DD + c) = v1;
            }
        }
    }
}

// ---------------- BN stats over g_buf1 ----------------
__global__ void stats_kernel() {
    __shared__ float s[2 * DD];
    int tid = threadIdx.x;
    if (tid < 2 * DD) s[tid] = 0.f;
    __syncthreads();
    float cs[4] = {0.f, 0.f, 0.f, 0.f}, cq[4] = {0.f, 0.f, 0.f, 0.f};
    int stride = gridDim.x * blockDim.x;
    for (int i = blockIdx.x * blockDim.x + tid; i < NN * DD / 4; i += stride) {
        float4 v = ((const float4*)g_buf1)[i];
        cs[0] += v.x; cq[0] += v.x * v.x;
        cs[1] += v.y; cq[1] += v.y * v.y;
        cs[2] += v.z; cq[2] += v.z * v.z;
        cs[3] += v.w; cq[3] += v.w * v.w;
    }
    int c4 = (tid & 31) * 4;
#pragma unroll
    for (int j = 0; j < 4; j++) {
        atomicAdd(&s[c4 + j], cs[j]);
        atomicAdd(&s[DD + c4 + j], cq[j]);
    }
    __syncthreads();
    if (tid < 2 * DD) atomicAdd(&g_stats[tid], s[tid]);
}

// ---------------- finalize + normalize ----------------
__global__ void finalize_kernel(const float* __restrict__ gamma,
                                const float* __restrict__ beta) {
    int c = threadIdx.x;
    float mean = g_stats[c] * (1.0f / NN);
    float var = g_stats[DD + c] * (1.0f / NN) - mean * mean;
    float sc = rsqrtf(var + BN_EPS) * gamma[c];
    g_scale[c] = sc;
    g_shift[c] = beta[c] - mean * sc;
}

__global__ void norm_kernel(float* __restrict__ out) {
    int i = blockIdx.x * blockDim.x + threadIdx.x;
    if (i >= NN * DD / 4) return;
    float4 v = ((const float4*)g_buf1)[i];
    float4 sc = ((const float4*)g_scale)[i & 31];
    float4 sh = ((const float4*)g_shift)[i & 31];
    v.x = v.x * sc.x + sh.x;
    v.y = v.y * sc.y + sh.y;
    v.z = v.z * sc.z + sh.z;
    v.w = v.w * sc.w + sh.w;
    ((float4*)out)[i] = v;
}

extern "C" void kernel_launch(void* const* d_in, const int* in_sizes, int n_in,
                              void* d_out, int out_size) {
    const float* x = (const float*)d_in[0];
    const void* ei = d_in[1];
    const float* ea = (const float*)d_in[2];
    const float* W1 = (const float*)d_in[3];
    const float* b1 = (const float*)d_in[4];
    const float* W2 = (const float*)d_in[5];
    const float* b2 = (const float*)d_in[6];
    const float* gamma = (const float*)d_in[7];
    const float* beta = (const float*)d_in[8];
    float* out = (float*)d_out;

    cudaFuncSetAttribute(mm_kernel<0>, cudaFuncAttributeMaxDynamicSharedMemorySize, MM_SMEM);
    cudaFuncSetAttribute(mm_kernel<1>, cudaFuncAttributeMaxDynamicSharedMemorySize, MM_SMEM);

    detect_kernel<<<1, 1>>>((const int*)ei);
    zero_kernel<<<(NN + 255) / 256, 256>>>();
    prep_w<<<dim3(DD, 2), DD>>>(W1, W2);
    convert_kernel<<<(EE + 255) / 256, 256>>>(ei);
    scan_kernel<<<1, 1024>>>();
    scatter_kernel<<<(EE + 255) / 256, 256>>>();
    agg_kernel<<<(NN * 32 + 255) / 256, 256>>>(x, ea);
    mm_kernel<0><<<(NN + 63) / 64, 256, MM_SMEM>>>(b1, x);
    mm_kernel<1><<<(NN + 63) / 64, 256, MM_SMEM>>>(b2, x);
    stats_kernel<<<592, 256>>>();
    finalize_kernel<<<1, DD>>>(gamma, beta);
    norm_kernel<<<(NN * DD / 4 + 255) / 256, 256>>>(out);
}

// round 8
// speedup vs baseline: 1.4131x; 1.0312x over previous
#include <cuda_runtime.h>
#include <cuda_bf16.h>
#include <cstdint>

#define NN 50000
#define DD 128
#define EE 800000
#define BN_EPS 1e-5f

// ---------------- scratch (no allocs allowed) ----------------
__device__ float g_buf1[NN * DD];          // agg -> h (pre-BN)
__device__ float g_buf2[NN * DD];          // t = relu(h@W1+b1)
__device__ float g_stats[2 * DD];
__device__ float g_scale[DD];
__device__ float g_shift[DD];
__device__ int g_is64;
__device__ __nv_bfloat16 g_w1hi[DD * DD];  // W^T hi/lo splits, [n][k] bf16
__device__ __nv_bfloat16 g_w1lo[DD * DD];
__device__ __nv_bfloat16 g_w2hi[DD * DD];
__device__ __nv_bfloat16 g_w2lo[DD * DD];
// CSR scratch
__device__ int g_src[EE];
__device__ int g_dst[EE];
__device__ int g_cnt[NN];
__device__ int g_off[NN];
__device__ int g_cursor[NN];
__device__ int2 g_pair[EE];                // {edge id, src} bucketed by dst

// ---------------- helpers ----------------
__device__ __forceinline__ uint32_t smem_u32(const void* p) {
    uint32_t a;
    asm("{ .reg .u64 t; cvta.to.shared.u64 t, %1; cvt.u32.u64 %0, t; }" : "=r"(a) : "l"(p));
    return a;
}
#define LDSM4(r, addr)                                                        \
    asm volatile("ldmatrix.sync.aligned.m8n8.x4.shared.b16 {%0,%1,%2,%3}, [%4];" \
                 : "=r"((r)[0]), "=r"((r)[1]), "=r"((r)[2]), "=r"((r)[3])     \
                 : "r"(addr))
#define MMA(ac, a, b0, b1)                                                    \
    asm volatile(                                                             \
        "mma.sync.aligned.m16n8k16.row.col.f32.bf16.bf16.f32 "                \
        "{%0,%1,%2,%3}, {%4,%5,%6,%7}, {%8,%9}, {%0,%1,%2,%3};"               \
        : "+f"((ac)[0]), "+f"((ac)[1]), "+f"((ac)[2]), "+f"((ac)[3])          \
        : "r"((a)[0]), "r"((a)[1]), "r"((a)[2]), "r"((a)[3]), "r"(b0), "r"(b1))

// ---------------- k_det: edge_index dtype probe ----------------
__global__ void detect_kernel(const int* __restrict__ ei32) {
    int zeros = 0;
    for (int i = 1; i < 256; i += 2) zeros += (ei32[i] == 0);
    g_is64 = (zeros >= 96) ? 1 : 0;
}

// ---------------- zero counters + stats (runs every replay) ----------------
__global__ void zero_kernel() {
    int i = blockIdx.x * blockDim.x + threadIdx.x;
    if (i < NN) g_cnt[i] = 0;
    if (i < 2 * DD) g_stats[i] = 0.f;
}

// ---------------- prep: W -> transposed bf16 hi/lo splits [n][k] ----------------
__global__ void prep_w(const float* __restrict__ W1, const float* __restrict__ W2) {
    const float* W = blockIdx.y ? W2 : W1;
    __nv_bfloat16* hi = blockIdx.y ? g_w2hi : g_w1hi;
    __nv_bfloat16* lo = blockIdx.y ? g_w2lo : g_w1lo;
    int k = blockIdx.x, n = threadIdx.x;
    float v = W[k * DD + n];
    __nv_bfloat16 h = __float2bfloat16(v);
    hi[n * DD + k] = h;
    lo[n * DD + k] = __float2bfloat16(v - __bfloat162float(h));
}

// ---------------- convert: edge_index -> int32 + dst histogram ----------------
__global__ void convert_kernel(const void* __restrict__ ei) {
    int e = blockIdx.x * blockDim.x + threadIdx.x;
    if (e >= EE) return;
    long long s, d;
    if (g_is64) {
        const long long* p = (const long long*)ei;
        s = p[e];
        d = p[EE + e];
    } else {
        const int* p = (const int*)ei;
        s = p[e];
        d = p[EE + e];
    }
    int si = (int)s, di = (int)d;
    if ((unsigned)si >= NN) si = 0;
    if ((unsigned)di >= NN) di = 0;
    g_src[e] = si;
    g_dst[e] = di;
    atomicAdd(&g_cnt[di], 1);
}

// ---------------- scan: exclusive prefix over g_cnt (1 CTA, 1024 thr) ----------------
__global__ void scan_kernel() {
    __shared__ int warp_sums[32];
    __shared__ int s_carry;
    int tid = threadIdx.x;
    if (tid == 0) s_carry = 0;
    __syncthreads();
    for (int base = 0; base < NN; base += 1024) {
        int i = base + tid;
        int v = (i < NN) ? g_cnt[i] : 0;
        int incl = v;
#pragma unroll
        for (int d = 1; d < 32; d <<= 1) {
            int t = __shfl_up_sync(0xFFFFFFFFu, incl, d);
            if ((tid & 31) >= d) incl += t;
        }
        if ((tid & 31) == 31) warp_sums[tid >> 5] = incl;
        __syncthreads();
        if (tid < 32) {
            int w = warp_sums[tid];
            int ws = w;
#pragma unroll
            for (int d = 1; d < 32; d <<= 1) {
                int t = __shfl_up_sync(0xFFFFFFFFu, ws, d);
                if (tid >= d) ws += t;
            }
            warp_sums[tid] = ws - w;  // exclusive warp offset
        }
        __syncthreads();
        int excl = incl - v + warp_sums[tid >> 5] + s_carry;
        if (i < NN) {
            g_off[i] = excl;
            g_cursor[i] = excl;
        }
        __syncthreads();
        if (tid == 1023) s_carry = excl + v;
        __syncthreads();
    }
}

// ---------------- scatter: bucket {edge, src} pairs by dst ----------------
__global__ void scatter_kernel() {
    int e = blockIdx.x * blockDim.x + threadIdx.x;
    if (e >= EE) return;
    int d = g_dst[e];
    int pos = atomicAdd(&g_cursor[d], 1);
    g_pair[pos] = make_int2(e, g_src[e]);
}

// ---------------- aggregate: warp per node, pipelined gather, no atomics ----------------
__global__ void agg_kernel(const float* __restrict__ x,
                           const float* __restrict__ ea) {
    int w = (blockIdx.x * blockDim.x + threadIdx.x) >> 5;
    int ln = threadIdx.x & 31;
    if (w >= NN) return;
    int beg = g_off[w];
    int cnt = g_cnt[w];
    int c = ln * 4;
    float4 acc = __ldg((const float4*)(x + (size_t)w * DD + c));  // h = x + agg
    const int2* pp = g_pair + beg;

    int2 p0, p1;
    if (cnt > 0) p0 = __ldg(pp);
    if (cnt > 1) p1 = __ldg(pp + 1);

    int i = 0;
    for (; i + 3 < cnt; i += 2) {
        int2 p2 = __ldg(pp + i + 2);
        int2 p3 = __ldg(pp + i + 3);
        float4 a0 = __ldcs((const float4*)(ea + (size_t)p0.x * DD + c));
        float4 b0 = __ldg((const float4*)(x + (size_t)p0.y * DD + c));
        float4 a1 = __ldcs((const float4*)(ea + (size_t)p1.x * DD + c));
        float4 b1 = __ldg((const float4*)(x + (size_t)p1.y * DD + c));
        acc.x += fmaxf(a0.x + b0.x, 0.f);
        acc.y += fmaxf(a0.y + b0.y, 0.f);
        acc.z += fmaxf(a0.z + b0.z, 0.f);
        acc.w += fmaxf(a0.w + b0.w, 0.f);
        acc.x += fmaxf(a1.x + b1.x, 0.f);
        acc.y += fmaxf(a1.y + b1.y, 0.f);
        acc.z += fmaxf(a1.z + b1.z, 0.f);
        acc.w += fmaxf(a1.w + b1.w, 0.f);
        p0 = p2;
        p1 = p3;
    }
    for (; i < cnt; i++) {
        int2 p = (i == 0) ? p0 : ((i == 1 && cnt > 1) ? p1 : __ldg(pp + i));
        // after the unrolled loop, p0/p1 hold pairs for i and i+1
        if (i + 1 < cnt || 1) {}
        p = p0;
        float4 a = __ldcs((const float4*)(ea + (size_t)p.x * DD + c));
        float4 b = __ldg((const float4*)(x + (size_t)p.y * DD + c));
        acc.x += fmaxf(a.x + b.x, 0.f);
        acc.y += fmaxf(a.y + b.y, 0.f);
        acc.z += fmaxf(a.z + b.z, 0.f);
        acc.w += fmaxf(a.w + b.w, 0.f);
        p0 = p1;
        if (i + 2 < cnt) p1 = __ldg(pp + i + 2);
    }
    *(float4*)(g_buf1 + (size_t)w * DD + c) = acc;
}

// ---------------- HMMA GEMM: 64x128 out tile per CTA, 2 CTAs/SM ----------------
#define AST 136
#define OF_AHI 1024u
#define OF_ALO (1024u + 17408u)
#define OF_BHI (1024u + 2u * 17408u)
#define OF_BLO (1024u + 2u * 17408u + 34816u)
#define MM_SMEM (1024 + 2 * 17408 + 2 * 34816)

template <int MODE>
__global__ void __launch_bounds__(256, 2) mm_kernel(const float* __restrict__ bias,
                                                    const float* __restrict__ resid) {
    extern __shared__ char smem[];
    const uint32_t sb = smem_u32(smem);
    float* sbias = (float*)smem;
    const int tid = threadIdx.x, wid = tid >> 5, ln = tid & 31;
    const int row0 = blockIdx.x * 64;

    const float* A = MODE ? g_buf2 : g_buf1;
    float* out = MODE ? g_buf1 : g_buf2;
    const __nv_bfloat16* Bhi = MODE ? g_w2hi : g_w1hi;
    const __nv_bfloat16* Blo = MODE ? g_w2lo : g_w1lo;

    if (tid < 128) sbias[tid] = bias[tid];

    {
        __nv_bfloat16* sAh = (__nv_bfloat16*)(smem + OF_AHI);
        __nv_bfloat16* sAl = (__nv_bfloat16*)(smem + OF_ALO);
#pragma unroll
        for (int rr = 0; rr < 8; rr++) {
            int r = wid * 8 + rr;
            int gr = row0 + r;
            float4 v = make_float4(0.f, 0.f, 0.f, 0.f);
            if (gr < NN) v = *(const float4*)(A + (size_t)gr * DD + ln * 4);
            __nv_bfloat16 hx = __float2bfloat16(v.x), hy = __float2bfloat16(v.y);
            __nv_bfloat16 hz = __float2bfloat16(v.z), hw = __float2bfloat16(v.w);
            __nv_bfloat162 hi0 = __halves2bfloat162(hx, hy);
            __nv_bfloat162 hi1 = __halves2bfloat162(hz, hw);
            __nv_bfloat162 lo0 = __halves2bfloat162(
                __float2bfloat16(v.x - __bfloat162float(hx)),
                __float2bfloat16(v.y - __bfloat162float(hy)));
            __nv_bfloat162 lo1 = __halves2bfloat162(
                __float2bfloat16(v.z - __bfloat162float(hz)),
                __float2bfloat16(v.w - __bfloat162float(hw)));
            int o = r * AST + ln * 4;
            *(__nv_bfloat162*)(sAh + o) = hi0;
            *(__nv_bfloat162*)(sAh + o + 2) = hi1;
            *(__nv_bfloat162*)(sAl + o) = lo0;
            *(__nv_bfloat162*)(sAl + o + 2) = lo1;
        }
    }
    {
        __nv_bfloat16* sBh = (__nv_bfloat16*)(smem + OF_BHI);
        __nv_bfloat16* sBl = (__nv_bfloat16*)(smem + OF_BLO);
#pragma unroll
        for (int rr = 0; rr < 16; rr++) {
            int n = wid * 16 + rr;
            uint2 vh = *(const uint2*)(Bhi + (size_t)n * DD + ln * 4);
            uint2 vl = *(const uint2*)(Blo + (size_t)n * DD + ln * 4);
            int o = n * AST + ln * 4;
            *(uint32_t*)((char*)sBh + (size_t)o * 2) = vh.x;
            *(uint32_t*)((char*)sBh + (size_t)o * 2 + 4) = vh.y;
            *(uint32_t*)((char*)sBl + (size_t)o * 2) = vl.x;
            *(uint32_t*)((char*)sBl + (size_t)o * 2 + 4) = vl.y;
        }
    }
    __syncthreads();

    const int m0 = (wid & 3) * 16;
    const int cb = (wid >> 2) * 64;
    const uint32_t a_off =
        (uint32_t)((m0 + ((ln >> 3) & 1) * 8 + (ln & 7)) * AST + ((ln >> 4) & 1) * 8) * 2u;
    const uint32_t b_off =
        (uint32_t)((cb + ((ln >> 4) & 1) * 8 + (ln & 7)) * AST + ((ln >> 3) & 1) * 8) * 2u;
    const uint32_t aAh = sb + OF_AHI + a_off, aAl = sb + OF_ALO + a_off;
    const uint32_t aBh = sb + OF_BHI + b_off, aBl = sb + OF_BLO + b_off;

    float acc[8][4];
#pragma unroll
    for (int f = 0; f < 8; f++)
#pragma unroll
        for (int j = 0; j < 4; j++) acc[f][j] = 0.f;

#pragma unroll
    for (int ks = 0; ks < 8; ks++) {
        const uint32_t kb = ks * 32u;
        uint32_t ah[4], al[4];
        LDSM4(ah, aAh + kb);
        LDSM4(al, aAl + kb);
#pragma unroll
        for (int nb = 0; nb < 4; nb++) {
            uint32_t bh[4], bl[4];
            const uint32_t bo = (uint32_t)(nb * 16 * AST) * 2u + kb;
            LDSM4(bh, aBh + bo);
            LDSM4(bl, aBl + bo);
            MMA(acc[2 * nb], ah, bh[0], bh[1]);
            MMA(acc[2 * nb + 1], ah, bh[2], bh[3]);
            MMA(acc[2 * nb], ah, bl[0], bl[1]);
            MMA(acc[2 * nb + 1], ah, bl[2], bl[3]);
            MMA(acc[2 * nb], al, bh[0], bh[1]);
            MMA(acc[2 * nb + 1], al, bh[2], bh[3]);
        }
    }

    const int gr0 = row0 + m0 + (ln >> 2);
    const int gr1 = gr0 + 8;
#pragma unroll
    for (int f = 0; f < 8; f++) {
        const int c = cb + f * 8 + (ln & 3) * 2;
        float2 v0 = make_float2(acc[f][0] + sbias[c], acc[f][1] + sbias[c + 1]);
        float2 v1 = make_float2(acc[f][2] + sbias[c], acc[f][3] + sbias[c + 1]);
        if (MODE == 0) {
            v0.x = fmaxf(v0.x, 0.f); v0.y = fmaxf(v0.y, 0.f);
            v1.x = fmaxf(v1.x, 0.f); v1.y = fmaxf(v1.y, 0.f);
            if (gr0 < NN) *(float2*)(out + (size_t)gr0 * DD + c) = v0;
            if (gr1 < NN) *(float2*)(out + (size_t)gr1 * DD + c) = v1;
        } else {
            if (gr0 < NN) {
                float2 r = *(const float2*)(resid + (size_t)gr0 * DD + c);
                v0.x += r.x; v0.y += r.y;
                *(float2*)(out + (size_t)gr0 * DD + c) = v0;
            }
            if (gr1 < NN) {
                float2 r = *(const float2*)(resid + (size_t)gr1 * DD + c);
                v1.x += r.x; v1.y += r.y;
                *(float2*)(out + (size_t)gr1 * DD + c) = v1;
            }
        }
    }
}

// ---------------- BN stats over g_buf1 ----------------
__global__ void stats_kernel() {
    __shared__ float s[2 * DD];
    int tid = threadIdx.x;
    if (tid < 2 * DD) s[tid] = 0.f;
    __syncthreads();
    float cs[4] = {0.f, 0.f, 0.f, 0.f}, cq[4] = {0.f, 0.f, 0.f, 0.f};
    int stride = gridDim.x * blockDim.x;
    for (int i = blockIdx.x * blockDim.x + tid; i < NN * DD / 4; i += stride) {
        float4 v = ((const float4*)g_buf1)[i];
        cs[0] += v.x; cq[0] += v.x * v.x;
        cs[1] += v.y; cq[1] += v.y * v.y;
        cs[2] += v.z; cq[2] += v.z * v.z;
        cs[3] += v.w; cq[3] += v.w * v.w;
    }
    int c4 = (tid & 31) * 4;
#pragma unroll
    for (int j = 0; j < 4; j++) {
        atomicAdd(&s[c4 + j], cs[j]);
        atomicAdd(&s[DD + c4 + j], cq[j]);
    }
    __syncthreads();
    if (tid < 2 * DD) atomicAdd(&g_stats[tid], s[tid]);
}

// ---------------- finalize + normalize ----------------
__global__ void finalize_kernel(const float* __restrict__ gamma,
                                const float* __restrict__ beta) {
    int c = threadIdx.x;
    float mean = g_stats[c] * (1.0f / NN);
    float var = g_stats[DD + c] * (1.0f / NN) - mean * mean;
    float sc = rsqrtf(var + BN_EPS) * gamma[c];
    g_scale[c] = sc;
    g_shift[c] = beta[c] - mean * sc;
}

__global__ void norm_kernel(float* __restrict__ out) {
    int i = blockIdx.x * blockDim.x + threadIdx.x;
    if (i >= NN * DD / 4) return;
    float4 v = ((const float4*)g_buf1)[i];
    float4 sc = ((const float4*)g_scale)[i & 31];
    float4 sh = ((const float4*)g_shift)[i & 31];
    v.x = v.x * sc.x + sh.x;
    v.y = v.y * sc.y + sh.y;
    v.z = v.z * sc.z + sh.z;
    v.w = v.w * sc.w + sh.w;
    ((float4*)out)[i] = v;
}

extern "C" void kernel_launch(void* const* d_in, const int* in_sizes, int n_in,
                              void* d_out, int out_size) {
    const float* x = (const float*)d_in[0];
    const void* ei = d_in[1];
    const float* ea = (const float*)d_in[2];
    const float* W1 = (const float*)d_in[3];
    const float* b1 = (const float*)d_in[4];
    const float* W2 = (const float*)d_in[5];
    const float* b2 = (const float*)d_in[6];
    const float* gamma = (const float*)d_in[7];
    const float* beta = (const float*)d_in[8];
    float* out = (float*)d_out;

    cudaFuncSetAttribute(mm_kernel<0>, cudaFuncAttributeMaxDynamicSharedMemorySize, MM_SMEM);
    cudaFuncSetAttribute(mm_kernel<1>, cudaFuncAttributeMaxDynamicSharedMemorySize, MM_SMEM);

    detect_kernel<<<1, 1>>>((const int*)ei);
    zero_kernel<<<(NN + 255) / 256, 256>>>();
    prep_w<<<dim3(DD, 2), DD>>>(W1, W2);
    convert_kernel<<<(EE + 255) / 256, 256>>>(ei);
    scan_kernel<<<1, 1024>>>();
    scatter_kernel<<<(EE + 255) / 256, 256>>>();
    agg_kernel<<<(NN * 32 + 255) / 256, 256>>>(x, ea);
    mm_kernel<0><<<(NN + 63) / 64, 256, MM_SMEM>>>(b1, x);
    mm_kernel<1><<<(NN + 63) / 64, 256, MM_SMEM>>>(b2, x);
    stats_kernel<<<592, 256>>>();
    finalize_kernel<<<1, DD>>>(gamma, beta);
    norm_kernel<<<(NN * DD / 4 + 255) / 256, 256>>>(out);
}